// round 2
// baseline (speedup 1.0000x reference)
#include <cuda_runtime.h>
#include <math.h>

#define DM   1024
#define NH   16
#define HD   64
#define BSZ  2
#define SL   1024
#define NTOK (BSZ*SL)   // 2048
#define NBH  (BSZ*NH)   // 32

// ---------------- device scratch (no cudaMalloc allowed) ----------------
__device__ float g_q[NBH*SL*HD];        // [bh][t][d]
__device__ float g_k[NBH*SL*HD];
__device__ float g_v[NBH*SL*HD];
__device__ float g_o[NBH*SL*HD];        // scan output, pre-RMS
__device__ float g_beta[NBH*SL];        // [bh][t]
__device__ float g_normed[NTOK*DM];     // rms-normed tokens, pre-Wo

// ---------------- GEMM: C = A(Mx1024) @ W^T, 128x128x16 tiles -----------
// mode 0: three projections (Wq,Wk,Wv), silu epilogue, transposed store
//         into g_q/g_k/g_v. grid.x = 24 (3 weights * 8 n-tiles).
// mode 1: plain store A=g_normed @ Wo^T -> Cplain. grid.x = 8.
__global__ __launch_bounds__(256) void gemm_kernel(
    const float* __restrict__ A,
    const float* __restrict__ W0,
    const float* __restrict__ W1,
    const float* __restrict__ W2,
    float* __restrict__ Cplain,
    int mode)
{
    const int K = DM;
    int which = 0, n0;
    const float* B;
    if (mode == 0) {
        which = blockIdx.x >> 3;
        n0 = (blockIdx.x & 7) * 128;
        B = (which == 0) ? W0 : (which == 1) ? W1 : W2;
    } else {
        n0 = blockIdx.x * 128;
        B = W0;
    }
    const float* Ap = (mode == 1) ? g_normed : A;
    int m0 = blockIdx.y * 128;

    __shared__ float As[16][132];
    __shared__ float Bs[16][132];

    int tid = threadIdx.x;
    int tx = tid & 15, ty = tid >> 4;

    float acc[8][8];
#pragma unroll
    for (int i = 0; i < 8; i++)
#pragma unroll
        for (int j = 0; j < 8; j++) acc[i][j] = 0.f;

    int lk = tid & 15, lr = tid >> 4;
    const float* Aptr = Ap + (m0 + lr) * K + lk;
    const float* Bptr = B  + (n0 + lr) * K + lk;

    for (int kt = 0; kt < K; kt += 16) {
#pragma unroll
        for (int r = 0; r < 8; r++) {
            As[lk][lr + 16*r] = Aptr[(16*r)*K + kt];
            Bs[lk][lr + 16*r] = Bptr[(16*r)*K + kt];
        }
        __syncthreads();
#pragma unroll
        for (int kk = 0; kk < 16; kk++) {
            float a[8], b[8];
#pragma unroll
            for (int i = 0; i < 8; i++) a[i] = As[kk][ty*8 + i];
#pragma unroll
            for (int j = 0; j < 8; j++) b[j] = Bs[kk][tx*8 + j];
#pragma unroll
            for (int i = 0; i < 8; i++)
#pragma unroll
                for (int j = 0; j < 8; j++)
                    acc[i][j] += a[i] * b[j];
        }
        __syncthreads();
    }

    if (mode == 0) {
        float* dst = (which == 0) ? g_q : (which == 1) ? g_k : g_v;
#pragma unroll
        for (int i = 0; i < 8; i++) {
            int m = m0 + ty*8 + i;
            int b_ = m >> 10, s_ = m & 1023;
#pragma unroll
            for (int j = 0; j < 8; j++) {
                int n = n0 + tx*8 + j;
                float xv = acc[i][j];
                float sv = xv / (1.f + expf(-xv));      // silu
                int h = n >> 6, d = n & 63;
                dst[(((b_ << 4) + h) * SL + s_) * HD + d] = sv;
            }
        }
    } else {
#pragma unroll
        for (int i = 0; i < 8; i++) {
            int m = m0 + ty*8 + i;
#pragma unroll
            for (int j = 0; j < 8; j++)
                Cplain[m * DM + n0 + tx*8 + j] = acc[i][j];
        }
    }
}

// ---------------- beta = 2*sigmoid(x @ Wb^T), per token -----------------
__global__ __launch_bounds__(128) void beta_kernel(
    const float* __restrict__ x, const float* __restrict__ Wb)
{
    __shared__ float xs[DM];
    __shared__ float pp[8][16];
    int m = blockIdx.x;   // token
#pragma unroll
    for (int i = threadIdx.x; i < DM/4; i += 128)
        ((float4*)xs)[i] = ((const float4*)(x + (size_t)m * DM))[i];
    __syncthreads();

    int h = threadIdx.x & 15;
    int slice = threadIdx.x >> 4;   // 0..7
    const float* w = Wb + h * DM;
    float p = 0.f;
    int k0 = slice * 128;
#pragma unroll 4
    for (int kk = 0; kk < 128; kk++) p += xs[k0 + kk] * w[k0 + kk];
    pp[slice][h] = p;
    __syncthreads();
    if (threadIdx.x < 16) {
        float s = 0.f;
#pragma unroll
        for (int j = 0; j < 8; j++) s += pp[j][threadIdx.x];
        float bsig = 2.f / (1.f + expf(-s));
        int b = m >> 10, t = m & 1023;
        g_beta[((b << 4) + threadIdx.x) * SL + t] = bsig;
    }
}

// ---------------- L2-normalize q and k rows (64-dim heads) --------------
__global__ __launch_bounds__(256) void l2norm_kernel()
{
    int gw = (blockIdx.x * blockDim.x + threadIdx.x) >> 5;  // warp id
    int lane = threadIdx.x & 31;
    if (gw >= 2 * NBH * SL) return;
    float* base = (gw < NBH * SL) ? g_q : g_k;
    int row = gw & (NBH * SL - 1);
    float2* p = (float2*)(base + (size_t)row * HD) + lane;
    float2 v = *p;
    float ss = v.x * v.x + v.y * v.y;
#pragma unroll
    for (int o = 16; o; o >>= 1) ss += __shfl_xor_sync(0xffffffffu, ss, o);
    float sc = 1.f / (sqrtf(ss) + 1e-6f);
    v.x *= sc; v.y *= sc;
    *p = v;
}

// ---------------- sequential delta scan, 1 block per (b,h) --------------
// Dual register-resident copies of M (row-owned + column-owned) so both
// matvec directions are thread-local dots; rank-1 update applied twice.
// thread = (seg in 0..3, c in 0..63):
//   Mcol[i] = M[seg*16+i][c]   Mrow[i] = M[c][seg*16+i]
__global__ __launch_bounds__(256) void scan_kernel()
{
    int bh = blockIdx.x;
    const float* q  = g_q + (size_t)bh * SL * HD;
    const float* k  = g_k + (size_t)bh * SL * HD;
    const float* v  = g_v + (size_t)bh * SL * HD;
    const float* bt = g_beta + (size_t)bh * SL;
    float* o        = g_o + (size_t)bh * SL * HD;

    int tid = threadIdx.x;
    int c = tid & 63;
    int seg = tid >> 6;

    float Mcol[16], Mrow[16];
#pragma unroll
    for (int i = 0; i < 16; i++) { Mcol[i] = 0.f; Mrow[i] = 0.f; }

    __shared__ float sq[16][64], sk[16][64], sv[16][64];
    __shared__ float sb[16];
    __shared__ float rp[4][64], op[4][64];
    __shared__ float sdelta[64];

    for (int t0 = 0; t0 < SL; t0 += 16) {
        __syncthreads();    // protect shared reuse across chunks
        ((float4*)sq)[tid] = ((const float4*)(q + t0 * HD))[tid];
        ((float4*)sk)[tid] = ((const float4*)(k + t0 * HD))[tid];
        ((float4*)sv)[tid] = ((const float4*)(v + t0 * HD))[tid];
        if (tid < 16) sb[tid] = bt[t0 + tid];
        __syncthreads();

#pragma unroll 1
        for (int tt = 0; tt < 16; tt++) {
            float kk[16], qq[16];
            *(float4*)&kk[0]  = *(const float4*)&sk[tt][seg*16];
            *(float4*)&kk[4]  = *(const float4*)&sk[tt][seg*16+4];
            *(float4*)&kk[8]  = *(const float4*)&sk[tt][seg*16+8];
            *(float4*)&kk[12] = *(const float4*)&sk[tt][seg*16+12];
            *(float4*)&qq[0]  = *(const float4*)&sq[tt][seg*16];
            *(float4*)&qq[4]  = *(const float4*)&sq[tt][seg*16+4];
            *(float4*)&qq[8]  = *(const float4*)&sq[tt][seg*16+8];
            *(float4*)&qq[12] = *(const float4*)&sq[tt][seg*16+12];

            float pr = 0.f, po = 0.f;
#pragma unroll
            for (int i = 0; i < 16; i++) {
                pr += Mrow[i] * kk[i];   // partial of r_c = (M k)_c
                po += qq[i] * Mcol[i];   // partial of out_c = (M^T q)_c
            }
            rp[seg][c] = pr;
            op[seg][c] = po;
            __syncthreads();

            if (tid < 64) {
                float rr = rp[0][tid] + rp[1][tid] + rp[2][tid] + rp[3][tid];
                sdelta[tid] = sv[tt][tid] - rr;          // delta = v - M k
            } else if (tid < 128) {
                int cc = tid - 64;
                o[(t0 + tt) * HD + cc] =
                    op[0][cc] + op[1][cc] + op[2][cc] + op[3][cc];
            }
            __syncthreads();

            float b_t  = sb[tt];
            float bdc  = b_t * sdelta[c];      // beta*delta[c] for col copy
            float brk  = b_t * sk[tt][c];      // beta*k[c]    for row copy
            float dd[16];
            *(float4*)&dd[0]  = *(const float4*)&sdelta[seg*16];
            *(float4*)&dd[4]  = *(const float4*)&sdelta[seg*16+4];
            *(float4*)&dd[8]  = *(const float4*)&sdelta[seg*16+8];
            *(float4*)&dd[12] = *(const float4*)&sdelta[seg*16+12];
#pragma unroll
            for (int i = 0; i < 16; i++) {
                Mcol[i] += kk[i] * bdc;   // M[x][c]  += beta*k[x]*delta[c]
                Mrow[i] += dd[i] * brk;   // M[c][y]  += beta*k[c]*delta[y]
            }
        }
    }
}

// ---------------- RMSNorm over gathered heads -> g_normed ---------------
__global__ __launch_bounds__(256) void rms_kernel(const float* __restrict__ rms_w)
{
    __shared__ float red[256];
    int m = blockIdx.x;             // token
    int b = m >> 10, t = m & 1023;
    int tid = threadIdx.x;
    int f = tid * 4;
    int h = f >> 6, d = f & 63;
    float4 v4 = *(const float4*)(g_o + ((((size_t)b*NH + h) * SL + t) * HD + d));
    float ss = v4.x*v4.x + v4.y*v4.y + v4.z*v4.z + v4.w*v4.w;
    red[tid] = ss;
    __syncthreads();
    for (int s = 128; s > 0; s >>= 1) {
        if (tid < s) red[tid] += red[tid + s];
        __syncthreads();
    }
    float inv = rsqrtf(red[0] * (1.f / 1024.f) + 1e-6f);
    float4 w4 = *(const float4*)(rms_w + f);
    float4 r;
    r.x = v4.x * inv * w4.x;
    r.y = v4.y * inv * w4.y;
    r.z = v4.z * inv * w4.z;
    r.w = v4.w * inv * w4.w;
    *(float4*)(g_normed + (size_t)m * DM + f) = r;
}

// ---------------------------- launch ------------------------------------
extern "C" void kernel_launch(void* const* d_in, const int* in_sizes, int n_in,
                              void* d_out, int out_size)
{
    const float* x     = (const float*)d_in[0];
    const float* Wq    = (const float*)d_in[1];
    const float* Wk    = (const float*)d_in[2];
    const float* Wv    = (const float*)d_in[3];
    const float* Wb    = (const float*)d_in[4];
    const float* Wo    = (const float*)d_in[5];
    const float* rms_w = (const float*)d_in[6];
    float* out = (float*)d_out;

    // 1) q/k/v projections + silu, transposed store
    {
        dim3 g(24, 16);
        gemm_kernel<<<g, 256>>>(x, Wq, Wk, Wv, nullptr, 0);
    }
    // 2) beta
    beta_kernel<<<NTOK, 128>>>(x, Wb);
    // 3) L2 norm of q and k heads
    {
        int warps = 2 * NBH * SL;            // 65536
        l2norm_kernel<<<warps / 8, 256>>>();
    }
    // 4) sequential delta scan
    scan_kernel<<<NBH, 256>>>();
    // 5) RMSNorm
    rms_kernel<<<NTOK, 256>>>(rms_w);
    // 6) output projection
    {
        dim3 g(8, 16);
        gemm_kernel<<<g, 256>>>(nullptr, Wo, nullptr, nullptr, out, 1);
    }
}

// round 5
// speedup vs baseline: 1.5026x; 1.5026x over previous
#include <cuda_runtime.h>
#include <cstdint>
#include <math.h>

#define DM   1024
#define NH   16
#define HD   64
#define BSZ  2
#define SL   1024
#define NTOK (BSZ*SL)   // 2048
#define NBH  (BSZ*NH)   // 32

// ---------------- device scratch (no cudaMalloc allowed) ----------------
// token-major: [token][DM]  (head h occupies cols h*64..h*64+63)
__device__ float g_q[NTOK*DM];
__device__ float g_k[NTOK*DM];
__device__ float g_v[NTOK*DM];
__device__ float g_o[NTOK*DM];
__device__ float g_beta[NBH*SL];        // [bh][t]
__device__ float g_normed[NTOK*DM];

// ---------------- helpers ------------------------------------------------
__device__ __forceinline__ uint32_t f2tf32(float f) {
    uint32_t r;
    asm("cvt.rna.tf32.f32 %0, %1;" : "=r"(r) : "f"(f));
    return r;
}
__device__ __forceinline__ void mma_tf32(float* d, const uint32_t* a, const uint32_t* b) {
    asm volatile(
        "mma.sync.aligned.m16n8k8.row.col.f32.tf32.tf32.f32 "
        "{%0,%1,%2,%3}, {%4,%5,%6,%7}, {%8,%9}, {%0,%1,%2,%3};\n"
        : "+f"(d[0]), "+f"(d[1]), "+f"(d[2]), "+f"(d[3])
        : "r"(a[0]), "r"(a[1]), "r"(a[2]), "r"(a[3]), "r"(b[0]), "r"(b[1]));
}
__device__ __forceinline__ float silu(float x) {
    return x / (1.f + __expf(-x));
}

// ================= tf32 mma.sync GEMM: C = A @ W^T =======================
// Block tile 128x128, 8 warps, warp tile 64x32 (4x4 m16n8k8 frags),
// K staged 16 at a time, double-buffered padded SMEM (stride 20 floats:
// bank-conflict-free for the m16n8k8 fragment pattern).
// mode 0: A=x, weights Wq/Wk/Wv; epilogue silu; store token-major q/k/v.
//         grid (24,16).
// mode 1: A=g_normed, W0=Wo; plain store to Cout. grid (8,16).
#define KST   16
#define NSTG  (DM/KST)   // 64
#define SSTR  20         // smem row stride (floats)

__global__ __launch_bounds__(256) void gemm_mma(
    const float* __restrict__ A,
    const float* __restrict__ W0,
    const float* __restrict__ W1,
    const float* __restrict__ W2,
    float* __restrict__ Cout, int mode)
{
    __shared__ __align__(16) float As[2][128*SSTR];
    __shared__ __align__(16) float Bs[2][128*SSTR];

    const int tid  = threadIdx.x;
    const int lane = tid & 31, wid = tid >> 5;
    const int gid  = lane >> 2, tg = lane & 3;
    const int wm   = wid & 1,  wn  = wid >> 1;   // 2 x 4 warp grid

    int which = 0, n0;
    const float* B;
    if (mode == 0) {
        which = blockIdx.x >> 3;
        n0 = (blockIdx.x & 7) * 128;
        B = (which == 0) ? W0 : (which == 1) ? W1 : W2;
    } else {
        n0 = blockIdx.x * 128;
        B = W0;
    }
    const float* Ap = (mode == 1) ? g_normed : A;
    const int m0 = blockIdx.y * 128;

    float acc[4][4][4];
#pragma unroll
    for (int mi = 0; mi < 4; mi++)
#pragma unroll
        for (int nj = 0; nj < 4; nj++)
#pragma unroll
            for (int e = 0; e < 4; e++) acc[mi][nj][e] = 0.f;

    // staging: each thread owns rows r0 and r0+64, 4 floats at col c40*4
    const int r0  = tid >> 2;
    const int c40 = tid & 3;
    const float* Aptr  = Ap + (size_t)(m0 + r0) * DM + c40 * 4;
    const float* Aptr2 = Aptr + (size_t)64 * DM;
    const float* Bptr  = B  + (size_t)(n0 + r0) * DM + c40 * 4;
    const float* Bptr2 = Bptr + (size_t)64 * DM;

    float4 ra0, ra1, rb0, rb1;
    auto ld = [&](int kt) {
        ra0 = *(const float4*)(Aptr  + kt * KST);
        ra1 = *(const float4*)(Aptr2 + kt * KST);
        rb0 = *(const float4*)(Bptr  + kt * KST);
        rb1 = *(const float4*)(Bptr2 + kt * KST);
    };
    auto st = [&](int s) {
        uint4 t;
        t.x = f2tf32(ra0.x); t.y = f2tf32(ra0.y); t.z = f2tf32(ra0.z); t.w = f2tf32(ra0.w);
        *(uint4*)&As[s][r0 * SSTR + c40 * 4] = t;
        t.x = f2tf32(ra1.x); t.y = f2tf32(ra1.y); t.z = f2tf32(ra1.z); t.w = f2tf32(ra1.w);
        *(uint4*)&As[s][(r0 + 64) * SSTR + c40 * 4] = t;
        t.x = f2tf32(rb0.x); t.y = f2tf32(rb0.y); t.z = f2tf32(rb0.z); t.w = f2tf32(rb0.w);
        *(uint4*)&Bs[s][r0 * SSTR + c40 * 4] = t;
        t.x = f2tf32(rb1.x); t.y = f2tf32(rb1.y); t.z = f2tf32(rb1.z); t.w = f2tf32(rb1.w);
        *(uint4*)&Bs[s][(r0 + 64) * SSTR + c40 * 4] = t;
    };

    ld(0); st(0);
    __syncthreads();

    for (int kt = 0; kt < NSTG; kt++) {
        const int s = kt & 1;
        if (kt + 1 < NSTG) ld(kt + 1);

        const float* as = &As[s][0];
        const float* bs = &Bs[s][0];
#pragma unroll
        for (int k8 = 0; k8 < 2; k8++) {
            const int kc = k8 * 8;
            uint32_t af[4][4], bf[4][2];
#pragma unroll
            for (int mi = 0; mi < 4; mi++) {
                int rb = (wm * 64 + mi * 16 + gid) * SSTR + kc + tg;
                af[mi][0] = __float_as_uint(as[rb]);
                af[mi][1] = __float_as_uint(as[rb + 8 * SSTR]);
                af[mi][2] = __float_as_uint(as[rb + 4]);
                af[mi][3] = __float_as_uint(as[rb + 8 * SSTR + 4]);
            }
#pragma unroll
            for (int nj = 0; nj < 4; nj++) {
                int nb = (wn * 32 + nj * 8 + gid) * SSTR + kc + tg;
                bf[nj][0] = __float_as_uint(bs[nb]);
                bf[nj][1] = __float_as_uint(bs[nb + 4]);
            }
#pragma unroll
            for (int mi = 0; mi < 4; mi++)
#pragma unroll
                for (int nj = 0; nj < 4; nj++)
                    mma_tf32(acc[mi][nj], af[mi], bf[nj]);
        }

        if (kt + 1 < NSTG) {
            __syncthreads();
            st(1 - s);
        }
        __syncthreads();
    }

    // ------------- epilogue -------------
    if (mode == 0) {
        float* dst = (which == 0) ? g_q : (which == 1) ? g_k : g_v;
#pragma unroll
        for (int mi = 0; mi < 4; mi++) {
            int r = m0 + wm * 64 + mi * 16 + gid;
#pragma unroll
            for (int nj = 0; nj < 4; nj++) {
                int cb = n0 + wn * 32 + nj * 8 + 2 * tg;
                float2 lo = make_float2(silu(acc[mi][nj][0]), silu(acc[mi][nj][1]));
                float2 hi = make_float2(silu(acc[mi][nj][2]), silu(acc[mi][nj][3]));
                *(float2*)(dst + (size_t)r * DM + cb)       = lo;
                *(float2*)(dst + (size_t)(r + 8) * DM + cb) = hi;
            }
        }
    } else {
#pragma unroll
        for (int mi = 0; mi < 4; mi++) {
            int r = m0 + wm * 64 + mi * 16 + gid;
#pragma unroll
            for (int nj = 0; nj < 4; nj++) {
                int cb = n0 + wn * 32 + nj * 8 + 2 * tg;
                *(float2*)(Cout + (size_t)r * DM + cb) =
                    make_float2(acc[mi][nj][0], acc[mi][nj][1]);
                *(float2*)(Cout + (size_t)(r + 8) * DM + cb) =
                    make_float2(acc[mi][nj][2], acc[mi][nj][3]);
            }
        }
    }
}

// ---------------- beta = 2*sigmoid(x @ Wb^T), per token -----------------
__global__ __launch_bounds__(128) void beta_kernel(
    const float* __restrict__ x, const float* __restrict__ Wb)
{
    __shared__ float xs[DM];
    __shared__ float pp[8][16];
    int m = blockIdx.x;
#pragma unroll
    for (int i = threadIdx.x; i < DM/4; i += 128)
        ((float4*)xs)[i] = ((const float4*)(x + (size_t)m * DM))[i];
    __syncthreads();

    int h = threadIdx.x & 15;
    int slice = threadIdx.x >> 4;
    const float* w = Wb + h * DM;
    float p = 0.f;
    int k0 = slice * 128;
#pragma unroll 4
    for (int kk = 0; kk < 128; kk++) p += xs[k0 + kk] * w[k0 + kk];
    pp[slice][h] = p;
    __syncthreads();
    if (threadIdx.x < 16) {
        float s = 0.f;
#pragma unroll
        for (int j = 0; j < 8; j++) s += pp[j][threadIdx.x];
        float bsig = 2.f / (1.f + expf(-s));
        int b = m >> 10, t = m & 1023;
        g_beta[((b << 4) + threadIdx.x) * SL + t] = bsig;
    }
}

// ---------------- L2-normalize q and k head rows (flat 64-float rows) ---
// token-major layout: head-row (m,h) is 64 contiguous floats at (m*16+h)*64.
__global__ __launch_bounds__(256) void l2norm_kernel()
{
    int gw = (blockIdx.x * blockDim.x + threadIdx.x) >> 5;  // warp id
    int lane = threadIdx.x & 31;
    if (gw >= 2 * NTOK * NH) return;
    float* base = (gw < NTOK * NH) ? g_q : g_k;
    int row = gw & (NTOK * NH - 1);
    float2* p = (float2*)(base + (size_t)row * HD) + lane;
    float2 v = *p;
    float ss = v.x * v.x + v.y * v.y;
#pragma unroll
    for (int o = 16; o; o >>= 1) ss += __shfl_xor_sync(0xffffffffu, ss, o);
    float sc = 1.f / (sqrtf(ss) + 1e-6f);
    v.x *= sc; v.y *= sc;
    *p = v;
}

// ---------------- sequential delta scan, 1 block per (b,h) --------------
__global__ __launch_bounds__(256) void scan_kernel()
{
    int bh = blockIdx.x;
    int b = bh >> 4, h = bh & 15;
    const size_t rowbase = (size_t)b * SL;
    const float* bt = g_beta + (size_t)bh * SL;

    int tid = threadIdx.x;
    int c = tid & 63;
    int seg = tid >> 6;

    float Mcol[16], Mrow[16];
#pragma unroll
    for (int i = 0; i < 16; i++) { Mcol[i] = 0.f; Mrow[i] = 0.f; }

    __shared__ float sq[16][64], sk[16][64], sv[16][64];
    __shared__ float sb[16];
    __shared__ float rp[4][64], op[4][64];
    __shared__ float sdelta[64];

    int rr = tid >> 4, c4 = tid & 15;

    for (int t0 = 0; t0 < SL; t0 += 16) {
        __syncthreads();
        {
            size_t roff = (rowbase + t0 + rr) * DM + h * HD;
            ((float4*)sq)[tid] = ((const float4*)(g_q + roff))[c4];
            ((float4*)sk)[tid] = ((const float4*)(g_k + roff))[c4];
            ((float4*)sv)[tid] = ((const float4*)(g_v + roff))[c4];
        }
        if (tid < 16) sb[tid] = bt[t0 + tid];
        __syncthreads();

#pragma unroll 1
        for (int tt = 0; tt < 16; tt++) {
            float kk[16], qq[16];
            *(float4*)&kk[0]  = *(const float4*)&sk[tt][seg*16];
            *(float4*)&kk[4]  = *(const float4*)&sk[tt][seg*16+4];
            *(float4*)&kk[8]  = *(const float4*)&sk[tt][seg*16+8];
            *(float4*)&kk[12] = *(const float4*)&sk[tt][seg*16+12];
            *(float4*)&qq[0]  = *(const float4*)&sq[tt][seg*16];
            *(float4*)&qq[4]  = *(const float4*)&sq[tt][seg*16+4];
            *(float4*)&qq[8]  = *(const float4*)&sq[tt][seg*16+8];
            *(float4*)&qq[12] = *(const float4*)&sq[tt][seg*16+12];

            float pr = 0.f, po = 0.f;
#pragma unroll
            for (int i = 0; i < 16; i++) {
                pr += Mrow[i] * kk[i];
                po += qq[i] * Mcol[i];
            }
            rp[seg][c] = pr;
            op[seg][c] = po;
            __syncthreads();

            if (tid < 64) {
                float rrv = rp[0][tid] + rp[1][tid] + rp[2][tid] + rp[3][tid];
                sdelta[tid] = sv[tt][tid] - rrv;
            } else if (tid < 128) {
                int cc = tid - 64;
                g_o[(rowbase + t0 + tt) * DM + h * HD + cc] =
                    op[0][cc] + op[1][cc] + op[2][cc] + op[3][cc];
            }
            __syncthreads();

            float b_t = sb[tt];
            float bdc = b_t * sdelta[c];
            float brk = b_t * sk[tt][c];
            float dd[16];
            *(float4*)&dd[0]  = *(const float4*)&sdelta[seg*16];
            *(float4*)&dd[4]  = *(const float4*)&sdelta[seg*16+4];
            *(float4*)&dd[8]  = *(const float4*)&sdelta[seg*16+8];
            *(float4*)&dd[12] = *(const float4*)&sdelta[seg*16+12];
#pragma unroll
            for (int i = 0; i < 16; i++) {
                Mcol[i] += kk[i] * bdc;
                Mrow[i] += dd[i] * brk;
            }
        }
    }
}

// ---------------- RMSNorm (token-major rows) -> g_normed ----------------
__global__ __launch_bounds__(256) void rms_kernel(const float* __restrict__ rms_w)
{
    __shared__ float red[256];
    int m = blockIdx.x;
    int tid = threadIdx.x;
    int f = tid * 4;
    float4 v4 = *(const float4*)(g_o + (size_t)m * DM + f);
    float ss = v4.x*v4.x + v4.y*v4.y + v4.z*v4.z + v4.w*v4.w;
    red[tid] = ss;
    __syncthreads();
    for (int s = 128; s > 0; s >>= 1) {
        if (tid < s) red[tid] += red[tid + s];
        __syncthreads();
    }
    float inv = rsqrtf(red[0] * (1.f / 1024.f) + 1e-6f);
    float4 w4 = *(const float4*)(rms_w + f);
    float4 r;
    r.x = v4.x * inv * w4.x;
    r.y = v4.y * inv * w4.y;
    r.z = v4.z * inv * w4.z;
    r.w = v4.w * inv * w4.w;
    *(float4*)(g_normed + (size_t)m * DM + f) = r;
}

// ---------------------------- launch ------------------------------------
extern "C" void kernel_launch(void* const* d_in, const int* in_sizes, int n_in,
                              void* d_out, int out_size)
{
    const float* x     = (const float*)d_in[0];
    const float* Wq    = (const float*)d_in[1];
    const float* Wk    = (const float*)d_in[2];
    const float* Wv    = (const float*)d_in[3];
    const float* Wb    = (const float*)d_in[4];
    const float* Wo    = (const float*)d_in[5];
    const float* rms_w = (const float*)d_in[6];
    float* out = (float*)d_out;

    // 1) q/k/v projections (tf32 tensor cores) + silu epilogue
    {
        dim3 g(24, 16);
        gemm_mma<<<g, 256>>>(x, Wq, Wk, Wv, nullptr, 0);
    }
    // 2) beta
    beta_kernel<<<NTOK, 128>>>(x, Wb);
    // 3) L2 norm of q and k heads
    l2norm_kernel<<<2 * NTOK * NH / 8, 256>>>();
    // 4) sequential delta scan
    scan_kernel<<<NBH, 256>>>();
    // 5) RMSNorm
    rms_kernel<<<NTOK, 256>>>(rms_w);
    // 6) output projection
    {
        dim3 g(8, 16);
        gemm_mma<<<g, 256>>>(nullptr, Wo, nullptr, nullptr, out, 1);
    }
}